// round 2
// baseline (speedup 1.0000x reference)
#include <cuda_runtime.h>
#include <math.h>

#define BATCH 4096
#define T 64
#define HID 256
#define INDIM 192

// Scratch: precomputed input projections [m][t*BATCH*HID], m = ff/gate/tau
__device__ float g_proj[3][(size_t)T * BATCH * HID];   // 3 x 256 MB
// Ping-pong hidden state
__device__ float g_h[2][BATCH * HID];                  // 2 x 4 MB

// ---------------- zero h0 ----------------
__global__ void zero_h_kernel() {
    int i = blockIdx.x * blockDim.x + threadIdx.x;
    if (i < BATCH * HID) g_h[0][i] = 0.f;
}

// ---------------- tiling config (shared by proj & step kernels) ----------------
#define BM 128
#define BN 64
#define BK 32
// 256 threads: thread (r,c) with r=tid>>4 (0..15), c=tid&15 (0..15)
// computes an 8x4 micro-tile: rows r*8.., cols c*4..

// ---------------- input projection GEMM ----------------
// Row m = t*BATCH + b (262144 rows), K = 192, three 256-wide outputs.
// A[m][i] = seq[b][t][i] = x[((b*3 + i/64)*64 + t)*64 + (i%64)]
__global__ __launch_bounds__(256, 1) void proj_kernel(
    const float* __restrict__ x,
    const float* __restrict__ wf, const float* __restrict__ bfa, const float* __restrict__ bfb,
    const float* __restrict__ wg, const float* __restrict__ bga, const float* __restrict__ bgb,
    const float* __restrict__ wt, const float* __restrict__ bta, const float* __restrict__ btb)
{
    __shared__ float As[BK][BM + 4];
    __shared__ float Bf[BK][BN + 4];
    __shared__ float Bg[BK][BN + 4];
    __shared__ float Bt[BK][BN + 4];

    const int row0 = blockIdx.x * BM;
    const int col0 = blockIdx.y * BN;
    const int tid  = threadIdx.x;
    const int r  = tid >> 4;
    const int c  = tid & 15;
    const int ki = tid & 31;   // k within tile
    const int si = tid >> 5;   // 0..7

    const int t  = row0 / BATCH;     // fixed per block (BATCH % BM == 0)
    const int b0 = row0 % BATCH;

    float accf[8][4] = {};
    float accg[8][4] = {};
    float acct[8][4] = {};

    for (int k0 = 0; k0 < INDIM; k0 += BK) {
        const int i  = k0 + ki;
        const int ch = i >> 6;
        const int w  = i & 63;
        #pragma unroll
        for (int p = 0; p < 16; p++) {
            int bb = b0 + si + p * 8;
            As[ki][si + p * 8] = x[(((bb * 3 + ch) << 6) + t) * 64 + w];
        }
        #pragma unroll
        for (int p = 0; p < 8; p++) {
            int j = col0 + si + p * 8;
            Bf[ki][si + p * 8] = wf[j * INDIM + i];
            Bg[ki][si + p * 8] = wg[j * INDIM + i];
            Bt[ki][si + p * 8] = wt[j * INDIM + i];
        }
        __syncthreads();
        #pragma unroll
        for (int kk = 0; kk < BK; kk++) {
            float4 a0 = *(const float4*)&As[kk][r * 8];
            float4 a1 = *(const float4*)&As[kk][r * 8 + 4];
            float4 vf = *(const float4*)&Bf[kk][c * 4];
            float4 vg = *(const float4*)&Bg[kk][c * 4];
            float4 vt = *(const float4*)&Bt[kk][c * 4];
            float av[8] = {a0.x, a0.y, a0.z, a0.w, a1.x, a1.y, a1.z, a1.w};
            #pragma unroll
            for (int ii = 0; ii < 8; ii++) {
                accf[ii][0] += av[ii] * vf.x; accf[ii][1] += av[ii] * vf.y;
                accf[ii][2] += av[ii] * vf.z; accf[ii][3] += av[ii] * vf.w;
                accg[ii][0] += av[ii] * vg.x; accg[ii][1] += av[ii] * vg.y;
                accg[ii][2] += av[ii] * vg.z; accg[ii][3] += av[ii] * vg.w;
                acct[ii][0] += av[ii] * vt.x; acct[ii][1] += av[ii] * vt.y;
                acct[ii][2] += av[ii] * vt.z; acct[ii][3] += av[ii] * vt.w;
            }
        }
        __syncthreads();
    }

    #pragma unroll
    for (int ii = 0; ii < 8; ii++) {
        int b = b0 + r * 8 + ii;
        size_t base = ((size_t)t * BATCH + b) * HID;
        #pragma unroll
        for (int jj = 0; jj < 4; jj++) {
            int hcol = col0 + c * 4 + jj;
            g_proj[0][base + hcol] = accf[ii][jj] + bfa[hcol] + bfb[hcol];
            g_proj[1][base + hcol] = accg[ii][jj] + bga[hcol] + bgb[hcol];
            g_proj[2][base + hcol] = acct[ii][jj] + bta[hcol] + btb[hcol];
        }
    }
}

// ---------------- recurrent step: 3 fused GEMMs [4096,256]x[256,256] + LTC update ----------------
__global__ __launch_bounds__(256, 1) void step_kernel(
    int t,
    const float* __restrict__ wf,
    const float* __restrict__ wg,
    const float* __restrict__ wt)
{
    const float* __restrict__ hin  = g_h[t & 1];
    float* __restrict__ hout       = g_h[(t + 1) & 1];

    __shared__ float As[BK][BM + 4];
    __shared__ float Bf[BK][BN + 4];
    __shared__ float Bg[BK][BN + 4];
    __shared__ float Bt[BK][BN + 4];

    const int b0   = blockIdx.x * BM;
    const int col0 = blockIdx.y * BN;
    const int tid  = threadIdx.x;
    const int r  = tid >> 4;
    const int c  = tid & 15;
    const int ki = tid & 31;
    const int si = tid >> 5;

    float accf[8][4] = {};
    float accg[8][4] = {};
    float acct[8][4] = {};

    for (int k0 = 0; k0 < HID; k0 += BK) {
        #pragma unroll
        for (int p = 0; p < 16; p++) {
            int bb = b0 + si + p * 8;
            As[ki][si + p * 8] = hin[bb * HID + k0 + ki];
        }
        #pragma unroll
        for (int p = 0; p < 8; p++) {
            int j = col0 + si + p * 8;
            Bf[ki][si + p * 8] = wf[j * HID + k0 + ki];
            Bg[ki][si + p * 8] = wg[j * HID + k0 + ki];
            Bt[ki][si + p * 8] = wt[j * HID + k0 + ki];
        }
        __syncthreads();
        #pragma unroll
        for (int kk = 0; kk < BK; kk++) {
            float4 a0 = *(const float4*)&As[kk][r * 8];
            float4 a1 = *(const float4*)&As[kk][r * 8 + 4];
            float4 vf = *(const float4*)&Bf[kk][c * 4];
            float4 vg = *(const float4*)&Bg[kk][c * 4];
            float4 vt = *(const float4*)&Bt[kk][c * 4];
            float av[8] = {a0.x, a0.y, a0.z, a0.w, a1.x, a1.y, a1.z, a1.w};
            #pragma unroll
            for (int ii = 0; ii < 8; ii++) {
                accf[ii][0] += av[ii] * vf.x; accf[ii][1] += av[ii] * vf.y;
                accf[ii][2] += av[ii] * vf.z; accf[ii][3] += av[ii] * vf.w;
                accg[ii][0] += av[ii] * vg.x; accg[ii][1] += av[ii] * vg.y;
                accg[ii][2] += av[ii] * vg.z; accg[ii][3] += av[ii] * vg.w;
                acct[ii][0] += av[ii] * vt.x; acct[ii][1] += av[ii] * vt.y;
                acct[ii][2] += av[ii] * vt.z; acct[ii][3] += av[ii] * vt.w;
            }
        }
        __syncthreads();
    }

    // fused LTC elementwise epilogue
    #pragma unroll
    for (int ii = 0; ii < 8; ii++) {
        int b = b0 + r * 8 + ii;
        size_t pbase = ((size_t)t * BATCH + b) * HID;
        #pragma unroll
        for (int jj = 0; jj < 4; jj++) {
            int j = col0 + c * 4 + jj;
            float hv   = hin[b * HID + j];
            float cand = tanhf(g_proj[0][pbase + j] + accf[ii][jj]);
            float gl   = g_proj[1][pbase + j] + accg[ii][jj];
            float gate = 1.f / (1.f + expf(-gl));
            float tl   = g_proj[2][pbase + j] + acct[ii][jj];
            float tau  = 0.5f + 1.5f / (1.f + expf(-tl));
            hout[b * HID + j] = tanhf(hv + (gate * cand - hv) / tau);
        }
    }
}

// ---------------- head: [4096,256] x [256,10] + bias, warp-per-output ----------------
__global__ void head_kernel(const float* __restrict__ hw,
                            const float* __restrict__ hb,
                            float* __restrict__ out)
{
    int gwarp = (blockIdx.x * blockDim.x + threadIdx.x) >> 5;
    int lane  = threadIdx.x & 31;
    if (gwarp >= BATCH * 10) return;
    int o = gwarp % 10;
    int b = gwarp / 10;
    const float* h = g_h[0];   // final state lands in buffer 0 after 64 steps
    float s = 0.f;
    #pragma unroll
    for (int k = lane; k < HID; k += 32)
        s += h[b * HID + k] * hw[o * HID + k];
    #pragma unroll
    for (int off = 16; off; off >>= 1)
        s += __shfl_down_sync(0xffffffffu, s, off);
    if (lane == 0) out[b * 10 + o] = s + hb[o];
}

extern "C" void kernel_launch(void* const* d_in, const int* in_sizes, int n_in,
                              void* d_out, int out_size)
{
    const float* x      = (const float*)d_in[0];
    const float* ffw    = (const float*)d_in[1];
    const float* ffb    = (const float*)d_in[2];
    const float* ffrw   = (const float*)d_in[3];
    const float* ffbias = (const float*)d_in[4];
    const float* gw     = (const float*)d_in[5];
    const float* gb     = (const float*)d_in[6];
    const float* grw    = (const float*)d_in[7];
    const float* gbias  = (const float*)d_in[8];
    const float* tw     = (const float*)d_in[9];
    const float* tb     = (const float*)d_in[10];
    const float* trw    = (const float*)d_in[11];
    const float* tbias  = (const float*)d_in[12];
    const float* hw     = (const float*)d_in[13];
    const float* hb     = (const float*)d_in[14];
    float* out = (float*)d_out;

    // h0 = 0 (must re-zero every call: deterministic replay)
    zero_h_kernel<<<(BATCH * HID + 255) / 256, 256>>>();

    // all input projections, batched over (t, b)
    dim3 pgrid((T * BATCH) / BM, HID / BN);
    proj_kernel<<<pgrid, 256>>>(x, ffw, ffb, ffbias, gw, gb, gbias, tw, tb, tbias);

    // 64 sequential LTC steps (ping-pong h buffers)
    dim3 sgrid(BATCH / BM, HID / BN);
    for (int t = 0; t < T; t++)
        step_kernel<<<sgrid, 256>>>(t, ffrw, grw, trw);

    // classifier head
    head_kernel<<<(BATCH * 10 * 32 + 255) / 256, 256>>>(hw, hb, out);
}

// round 3
// speedup vs baseline: 1.0005x; 1.0005x over previous
#include <cuda_runtime.h>
#include <math.h>

#define BATCH 4096
#define T 64
#define HID 256
#define INDIM 192

// Scratch: precomputed input projections [m][t*BATCH*HID], m = ff/gate/tau
__device__ float g_proj[3][(size_t)T * BATCH * HID];   // 3 x 256 MB
// Ping-pong hidden state
__device__ float g_h[2][BATCH * HID];                  // 2 x 4 MB

// ---------------- zero h0 ----------------
__global__ void zero_h_kernel() {
    int i = blockIdx.x * blockDim.x + threadIdx.x;
    if (i < BATCH * HID) g_h[0][i] = 0.f;
}

// ---------------- tiling config (shared by proj & step kernels) ----------------
#define BM 128
#define BN 64
#define BK 32
// 256 threads: thread (r,c) with r=tid>>4 (0..15), c=tid&15 (0..15)
// computes an 8x4 micro-tile: rows r*8.., cols c*4..

// ---------------- input projection GEMM ----------------
// Row m = t*BATCH + b (262144 rows), K = 192, three 256-wide outputs.
// A[m][i] = seq[b][t][i] = x[((b*3 + i/64)*64 + t)*64 + (i%64)]
__global__ __launch_bounds__(256, 1) void proj_kernel(
    const float* __restrict__ x,
    const float* __restrict__ wf, const float* __restrict__ bfa, const float* __restrict__ bfb,
    const float* __restrict__ wg, const float* __restrict__ bga, const float* __restrict__ bgb,
    const float* __restrict__ wt, const float* __restrict__ bta, const float* __restrict__ btb)
{
    __shared__ float As[BK][BM + 4];
    __shared__ float Bf[BK][BN + 4];
    __shared__ float Bg[BK][BN + 4];
    __shared__ float Bt[BK][BN + 4];

    const int row0 = blockIdx.x * BM;
    const int col0 = blockIdx.y * BN;
    const int tid  = threadIdx.x;
    const int r  = tid >> 4;
    const int c  = tid & 15;
    const int ki = tid & 31;   // k within tile
    const int si = tid >> 5;   // 0..7

    const int t  = row0 / BATCH;     // fixed per block (BATCH % BM == 0)
    const int b0 = row0 % BATCH;

    float accf[8][4] = {};
    float accg[8][4] = {};
    float acct[8][4] = {};

    for (int k0 = 0; k0 < INDIM; k0 += BK) {
        const int i  = k0 + ki;
        const int ch = i >> 6;
        const int w  = i & 63;
        #pragma unroll
        for (int p = 0; p < 16; p++) {
            int bb = b0 + si + p * 8;
            As[ki][si + p * 8] = x[(((bb * 3 + ch) << 6) + t) * 64 + w];
        }
        #pragma unroll
        for (int p = 0; p < 8; p++) {
            int j = col0 + si + p * 8;
            Bf[ki][si + p * 8] = wf[j * INDIM + i];
            Bg[ki][si + p * 8] = wg[j * INDIM + i];
            Bt[ki][si + p * 8] = wt[j * INDIM + i];
        }
        __syncthreads();
        #pragma unroll
        for (int kk = 0; kk < BK; kk++) {
            float4 a0 = *(const float4*)&As[kk][r * 8];
            float4 a1 = *(const float4*)&As[kk][r * 8 + 4];
            float4 vf = *(const float4*)&Bf[kk][c * 4];
            float4 vg = *(const float4*)&Bg[kk][c * 4];
            float4 vt = *(const float4*)&Bt[kk][c * 4];
            float av[8] = {a0.x, a0.y, a0.z, a0.w, a1.x, a1.y, a1.z, a1.w};
            #pragma unroll
            for (int ii = 0; ii < 8; ii++) {
                accf[ii][0] += av[ii] * vf.x; accf[ii][1] += av[ii] * vf.y;
                accf[ii][2] += av[ii] * vf.z; accf[ii][3] += av[ii] * vf.w;
                accg[ii][0] += av[ii] * vg.x; accg[ii][1] += av[ii] * vg.y;
                accg[ii][2] += av[ii] * vg.z; accg[ii][3] += av[ii] * vg.w;
                acct[ii][0] += av[ii] * vt.x; acct[ii][1] += av[ii] * vt.y;
                acct[ii][2] += av[ii] * vt.z; acct[ii][3] += av[ii] * vt.w;
            }
        }
        __syncthreads();
    }

    #pragma unroll
    for (int ii = 0; ii < 8; ii++) {
        int b = b0 + r * 8 + ii;
        size_t base = ((size_t)t * BATCH + b) * HID;
        #pragma unroll
        for (int jj = 0; jj < 4; jj++) {
            int hcol = col0 + c * 4 + jj;
            g_proj[0][base + hcol] = accf[ii][jj] + bfa[hcol] + bfb[hcol];
            g_proj[1][base + hcol] = accg[ii][jj] + bga[hcol] + bgb[hcol];
            g_proj[2][base + hcol] = acct[ii][jj] + bta[hcol] + btb[hcol];
        }
    }
}

// ---------------- recurrent step: 3 fused GEMMs [4096,256]x[256,256] + LTC update ----------------
__global__ __launch_bounds__(256, 1) void step_kernel(
    int t,
    const float* __restrict__ wf,
    const float* __restrict__ wg,
    const float* __restrict__ wt)
{
    const float* __restrict__ hin  = g_h[t & 1];
    float* __restrict__ hout       = g_h[(t + 1) & 1];

    __shared__ float As[BK][BM + 4];
    __shared__ float Bf[BK][BN + 4];
    __shared__ float Bg[BK][BN + 4];
    __shared__ float Bt[BK][BN + 4];

    const int b0   = blockIdx.x * BM;
    const int col0 = blockIdx.y * BN;
    const int tid  = threadIdx.x;
    const int r  = tid >> 4;
    const int c  = tid & 15;
    const int ki = tid & 31;
    const int si = tid >> 5;

    float accf[8][4] = {};
    float accg[8][4] = {};
    float acct[8][4] = {};

    for (int k0 = 0; k0 < HID; k0 += BK) {
        #pragma unroll
        for (int p = 0; p < 16; p++) {
            int bb = b0 + si + p * 8;
            As[ki][si + p * 8] = hin[bb * HID + k0 + ki];
        }
        #pragma unroll
        for (int p = 0; p < 8; p++) {
            int j = col0 + si + p * 8;
            Bf[ki][si + p * 8] = wf[j * HID + k0 + ki];
            Bg[ki][si + p * 8] = wg[j * HID + k0 + ki];
            Bt[ki][si + p * 8] = wt[j * HID + k0 + ki];
        }
        __syncthreads();
        #pragma unroll
        for (int kk = 0; kk < BK; kk++) {
            float4 a0 = *(const float4*)&As[kk][r * 8];
            float4 a1 = *(const float4*)&As[kk][r * 8 + 4];
            float4 vf = *(const float4*)&Bf[kk][c * 4];
            float4 vg = *(const float4*)&Bg[kk][c * 4];
            float4 vt = *(const float4*)&Bt[kk][c * 4];
            float av[8] = {a0.x, a0.y, a0.z, a0.w, a1.x, a1.y, a1.z, a1.w};
            #pragma unroll
            for (int ii = 0; ii < 8; ii++) {
                accf[ii][0] += av[ii] * vf.x; accf[ii][1] += av[ii] * vf.y;
                accf[ii][2] += av[ii] * vf.z; accf[ii][3] += av[ii] * vf.w;
                accg[ii][0] += av[ii] * vg.x; accg[ii][1] += av[ii] * vg.y;
                accg[ii][2] += av[ii] * vg.z; accg[ii][3] += av[ii] * vg.w;
                acct[ii][0] += av[ii] * vt.x; acct[ii][1] += av[ii] * vt.y;
                acct[ii][2] += av[ii] * vt.z; acct[ii][3] += av[ii] * vt.w;
            }
        }
        __syncthreads();
    }

    // fused LTC elementwise epilogue
    #pragma unroll
    for (int ii = 0; ii < 8; ii++) {
        int b = b0 + r * 8 + ii;
        size_t pbase = ((size_t)t * BATCH + b) * HID;
        #pragma unroll
        for (int jj = 0; jj < 4; jj++) {
            int j = col0 + c * 4 + jj;
            float hv   = hin[b * HID + j];
            float cand = tanhf(g_proj[0][pbase + j] + accf[ii][jj]);
            float gl   = g_proj[1][pbase + j] + accg[ii][jj];
            float gate = 1.f / (1.f + expf(-gl));
            float tl   = g_proj[2][pbase + j] + acct[ii][jj];
            float tau  = 0.5f + 1.5f / (1.f + expf(-tl));
            hout[b * HID + j] = tanhf(hv + (gate * cand - hv) / tau);
        }
    }
}

// ---------------- head: [4096,256] x [256,10] + bias, warp-per-output ----------------
__global__ void head_kernel(const float* __restrict__ hw,
                            const float* __restrict__ hb,
                            float* __restrict__ out)
{
    int gwarp = (blockIdx.x * blockDim.x + threadIdx.x) >> 5;
    int lane  = threadIdx.x & 31;
    if (gwarp >= BATCH * 10) return;
    int o = gwarp % 10;
    int b = gwarp / 10;
    const float* h = g_h[0];   // final state lands in buffer 0 after 64 steps
    float s = 0.f;
    #pragma unroll
    for (int k = lane; k < HID; k += 32)
        s += h[b * HID + k] * hw[o * HID + k];
    #pragma unroll
    for (int off = 16; off; off >>= 1)
        s += __shfl_down_sync(0xffffffffu, s, off);
    if (lane == 0) out[b * 10 + o] = s + hb[o];
}

extern "C" void kernel_launch(void* const* d_in, const int* in_sizes, int n_in,
                              void* d_out, int out_size)
{
    const float* x      = (const float*)d_in[0];
    const float* ffw    = (const float*)d_in[1];
    const float* ffb    = (const float*)d_in[2];
    const float* ffrw   = (const float*)d_in[3];
    const float* ffbias = (const float*)d_in[4];
    const float* gw     = (const float*)d_in[5];
    const float* gb     = (const float*)d_in[6];
    const float* grw    = (const float*)d_in[7];
    const float* gbias  = (const float*)d_in[8];
    const float* tw     = (const float*)d_in[9];
    const float* tb     = (const float*)d_in[10];
    const float* trw    = (const float*)d_in[11];
    const float* tbias  = (const float*)d_in[12];
    const float* hw     = (const float*)d_in[13];
    const float* hb     = (const float*)d_in[14];
    float* out = (float*)d_out;

    // h0 = 0 (must re-zero every call: deterministic replay)
    zero_h_kernel<<<(BATCH * HID + 255) / 256, 256>>>();

    // all input projections, batched over (t, b)
    dim3 pgrid((T * BATCH) / BM, HID / BN);
    proj_kernel<<<pgrid, 256>>>(x, ffw, ffb, ffbias, gw, gb, gbias, tw, tb, tbias);

    // 64 sequential LTC steps (ping-pong h buffers)
    dim3 sgrid(BATCH / BM, HID / BN);
    for (int t = 0; t < T; t++)
        step_kernel<<<sgrid, 256>>>(t, ffrw, grw, trw);

    // classifier head
    head_kernel<<<(BATCH * 10 * 32 + 255) / 256, 256>>>(hw, hb, out);
}

// round 4
// speedup vs baseline: 1.1930x; 1.1925x over previous
#include <cuda_runtime.h>
#include <math.h>

#define BATCH 4096
#define T 64
#define HID 256
#define INDIM 192

// Scratch: precomputed input projections [m][t*BATCH*HID], m = ff/gate/tau
__device__ float g_proj[3][(size_t)T * BATCH * HID];   // 3 x 256 MB
// Ping-pong hidden state
__device__ float g_h[2][BATCH * HID];                  // 2 x 4 MB

// ---------------- Blackwell packed fp32 helpers ----------------
__device__ __forceinline__ void fma2(unsigned long long& d,
                                     unsigned long long a,
                                     unsigned long long b) {
    asm("fma.rn.f32x2 %0, %1, %2, %0;" : "+l"(d) : "l"(a), "l"(b));
}
__device__ __forceinline__ unsigned long long dup2(float x) {
    unsigned long long r;
    asm("mov.b64 %0, {%1, %1};" : "=l"(r) : "f"(x));
    return r;
}
__device__ __forceinline__ void unpack2(unsigned long long v, float& lo, float& hi) {
    asm("mov.b64 {%0, %1}, %2;" : "=f"(lo), "=f"(hi) : "l"(v));
}

// ---------------- zero h0 ----------------
__global__ void zero_h_kernel() {
    int i = blockIdx.x * blockDim.x + threadIdx.x;
    if (i < BATCH * HID) g_h[0][i] = 0.f;
}

// ---------------- tiling config ----------------
#define BM 128
#define BN 64
#define BK 16
// 256 threads: thread (r,c), r=tid>>4 (0..15), c=tid&15 (0..15)
// computes an 8x4 micro-tile (x3 matrices): rows r*8.., cols c*4..
// loaders: ki=tid&15 (k in tile), si=tid>>4 (0..15)

// =========================================================================
// input projection GEMM: rows m = t*BATCH+b (262144), K=192, 3x 256-wide out
// A[m][i] = seq[b][t][i] = x[((b*3 + i/64)*64 + t)*64 + (i%64)]
// =========================================================================
__global__ __launch_bounds__(256, 1) void proj_kernel(
    const float* __restrict__ x,
    const float* __restrict__ wf, const float* __restrict__ bfa, const float* __restrict__ bfb,
    const float* __restrict__ wg, const float* __restrict__ bga, const float* __restrict__ bgb,
    const float* __restrict__ wt, const float* __restrict__ bta, const float* __restrict__ btb)
{
    __shared__ __align__(16) float As[2][BK][BM + 4];
    __shared__ __align__(16) float Bf[2][BK][BN + 4];
    __shared__ __align__(16) float Bg[2][BK][BN + 4];
    __shared__ __align__(16) float Bt[2][BK][BN + 4];

    const int row0 = blockIdx.x * BM;
    const int col0 = blockIdx.y * BN;
    const int tid  = threadIdx.x;
    const int r  = tid >> 4;
    const int c  = tid & 15;
    const int ki = tid & 15;
    const int si = tid >> 4;

    const int t  = row0 / BATCH;
    const int b0 = row0 % BATCH;

    unsigned long long accf[8][2] = {};
    unsigned long long accg[8][2] = {};
    unsigned long long acct[8][2] = {};

    float aR[8], bRf[4], bRg[4], bRt[4];

    auto load_tile = [&](int k0) {
        const int i  = k0 + ki;
        const int ch = i >> 6;
        const int w  = i & 63;
        #pragma unroll
        for (int p = 0; p < 8; p++) {
            int bb = b0 + si + p * 16;
            aR[p] = x[(((bb * 3 + ch) << 6) + t) * 64 + w];
        }
        #pragma unroll
        for (int p = 0; p < 4; p++) {
            int j = col0 + si + p * 16;
            bRf[p] = wf[j * INDIM + i];
            bRg[p] = wg[j * INDIM + i];
            bRt[p] = wt[j * INDIM + i];
        }
    };
    auto sts_tile = [&](int buf) {
        #pragma unroll
        for (int p = 0; p < 8; p++) As[buf][ki][si + p * 16] = aR[p];
        #pragma unroll
        for (int p = 0; p < 4; p++) {
            Bf[buf][ki][si + p * 16] = bRf[p];
            Bg[buf][ki][si + p * 16] = bRg[p];
            Bt[buf][ki][si + p * 16] = bRt[p];
        }
    };

    const int NT = INDIM / BK;   // 12
    load_tile(0);
    sts_tile(0);
    __syncthreads();

    for (int kt = 0; kt < NT; kt++) {
        const int cur = kt & 1;
        if (kt + 1 < NT) load_tile((kt + 1) * BK);
        #pragma unroll
        for (int kk = 0; kk < BK; kk++) {
            float4 a0 = *(const float4*)&As[cur][kk][r * 8];
            float4 a1 = *(const float4*)&As[cur][kk][r * 8 + 4];
            ulonglong2 vf = *(const ulonglong2*)&Bf[cur][kk][c * 4];
            ulonglong2 vg = *(const ulonglong2*)&Bg[cur][kk][c * 4];
            ulonglong2 vt = *(const ulonglong2*)&Bt[cur][kk][c * 4];
            float av[8] = {a0.x, a0.y, a0.z, a0.w, a1.x, a1.y, a1.z, a1.w};
            #pragma unroll
            for (int ii = 0; ii < 8; ii++) {
                unsigned long long ad = dup2(av[ii]);
                fma2(accf[ii][0], ad, vf.x); fma2(accf[ii][1], ad, vf.y);
                fma2(accg[ii][0], ad, vg.x); fma2(accg[ii][1], ad, vg.y);
                fma2(acct[ii][0], ad, vt.x); fma2(acct[ii][1], ad, vt.y);
            }
        }
        if (kt + 1 < NT) {
            __syncthreads();
            sts_tile(cur ^ 1);
            __syncthreads();
        }
    }

    // epilogue: add biases, write the three projection streams
    const int hc = col0 + c * 4;
    float4 biasf = make_float4(bfa[hc] + bfb[hc], bfa[hc+1] + bfb[hc+1],
                               bfa[hc+2] + bfb[hc+2], bfa[hc+3] + bfb[hc+3]);
    float4 biasg = make_float4(bga[hc] + bgb[hc], bga[hc+1] + bgb[hc+1],
                               bga[hc+2] + bgb[hc+2], bga[hc+3] + bgb[hc+3]);
    float4 biast = make_float4(bta[hc] + btb[hc], bta[hc+1] + btb[hc+1],
                               bta[hc+2] + btb[hc+2], bta[hc+3] + btb[hc+3]);
    #pragma unroll
    for (int ii = 0; ii < 8; ii++) {
        int b = b0 + r * 8 + ii;
        size_t base = ((size_t)t * BATCH + b) * HID + hc;
        float4 vfo, vgo, vto;
        unpack2(accf[ii][0], vfo.x, vfo.y); unpack2(accf[ii][1], vfo.z, vfo.w);
        unpack2(accg[ii][0], vgo.x, vgo.y); unpack2(accg[ii][1], vgo.z, vgo.w);
        unpack2(acct[ii][0], vto.x, vto.y); unpack2(acct[ii][1], vto.z, vto.w);
        vfo.x += biasf.x; vfo.y += biasf.y; vfo.z += biasf.z; vfo.w += biasf.w;
        vgo.x += biasg.x; vgo.y += biasg.y; vgo.z += biasg.z; vgo.w += biasg.w;
        vto.x += biast.x; vto.y += biast.y; vto.z += biast.z; vto.w += biast.w;
        *(float4*)&g_proj[0][base] = vfo;
        *(float4*)&g_proj[1][base] = vgo;
        *(float4*)&g_proj[2][base] = vto;
    }
}

// =========================================================================
// recurrent step: 3 fused GEMMs [4096,256]x[256,256] + LTC update
// =========================================================================
__global__ __launch_bounds__(256, 1) void step_kernel(
    int t,
    const float* __restrict__ wf,
    const float* __restrict__ wg,
    const float* __restrict__ wt)
{
    const float* __restrict__ hin = g_h[t & 1];
    float* __restrict__ hout      = g_h[(t + 1) & 1];

    __shared__ __align__(16) float As[2][BK][BM + 4];
    __shared__ __align__(16) float Bf[2][BK][BN + 4];
    __shared__ __align__(16) float Bg[2][BK][BN + 4];
    __shared__ __align__(16) float Bt[2][BK][BN + 4];

    const int b0   = blockIdx.x * BM;
    const int col0 = blockIdx.y * BN;
    const int tid  = threadIdx.x;
    const int r  = tid >> 4;
    const int c  = tid & 15;
    const int ki = tid & 15;
    const int si = tid >> 4;

    unsigned long long accf[8][2] = {};
    unsigned long long accg[8][2] = {};
    unsigned long long acct[8][2] = {};

    float aR[8], bRf[4], bRg[4], bRt[4];

    auto load_tile = [&](int k0) {
        #pragma unroll
        for (int p = 0; p < 8; p++) {
            int bb = b0 + si + p * 16;
            aR[p] = hin[bb * HID + k0 + ki];
        }
        #pragma unroll
        for (int p = 0; p < 4; p++) {
            int j = col0 + si + p * 16;
            bRf[p] = wf[j * HID + k0 + ki];
            bRg[p] = wg[j * HID + k0 + ki];
            bRt[p] = wt[j * HID + k0 + ki];
        }
    };
    auto sts_tile = [&](int buf) {
        #pragma unroll
        for (int p = 0; p < 8; p++) As[buf][ki][si + p * 16] = aR[p];
        #pragma unroll
        for (int p = 0; p < 4; p++) {
            Bf[buf][ki][si + p * 16] = bRf[p];
            Bg[buf][ki][si + p * 16] = bRg[p];
            Bt[buf][ki][si + p * 16] = bRt[p];
        }
    };

    const int NT = HID / BK;   // 16
    load_tile(0);
    sts_tile(0);
    __syncthreads();

    for (int kt = 0; kt < NT; kt++) {
        const int cur = kt & 1;
        if (kt + 1 < NT) load_tile((kt + 1) * BK);
        #pragma unroll
        for (int kk = 0; kk < BK; kk++) {
            float4 a0 = *(const float4*)&As[cur][kk][r * 8];
            float4 a1 = *(const float4*)&As[cur][kk][r * 8 + 4];
            ulonglong2 vf = *(const ulonglong2*)&Bf[cur][kk][c * 4];
            ulonglong2 vg = *(const ulonglong2*)&Bg[cur][kk][c * 4];
            ulonglong2 vt = *(const ulonglong2*)&Bt[cur][kk][c * 4];
            float av[8] = {a0.x, a0.y, a0.z, a0.w, a1.x, a1.y, a1.z, a1.w};
            #pragma unroll
            for (int ii = 0; ii < 8; ii++) {
                unsigned long long ad = dup2(av[ii]);
                fma2(accf[ii][0], ad, vf.x); fma2(accf[ii][1], ad, vf.y);
                fma2(accg[ii][0], ad, vg.x); fma2(accg[ii][1], ad, vg.y);
                fma2(acct[ii][0], ad, vt.x); fma2(acct[ii][1], ad, vt.y);
            }
        }
        if (kt + 1 < NT) {
            __syncthreads();
            sts_tile(cur ^ 1);
            __syncthreads();
        }
    }

    // fused LTC elementwise epilogue (fast exp; fp32)
    const int hc = col0 + c * 4;
    #pragma unroll
    for (int ii = 0; ii < 8; ii++) {
        int b = b0 + r * 8 + ii;
        size_t pbase = ((size_t)t * BATCH + b) * HID + hc;
        float4 pf = *(const float4*)&g_proj[0][pbase];
        float4 pg = *(const float4*)&g_proj[1][pbase];
        float4 pt = *(const float4*)&g_proj[2][pbase];
        float4 hv = *(const float4*)&hin[b * HID + hc];
        float rf[4], rg[4], rt[4], hvv[4], out[4];
        unpack2(accf[ii][0], rf[0], rf[1]); unpack2(accf[ii][1], rf[2], rf[3]);
        unpack2(accg[ii][0], rg[0], rg[1]); unpack2(accg[ii][1], rg[2], rg[3]);
        unpack2(acct[ii][0], rt[0], rt[1]); unpack2(acct[ii][1], rt[2], rt[3]);
        float pfv[4] = {pf.x, pf.y, pf.z, pf.w};
        float pgv[4] = {pg.x, pg.y, pg.z, pg.w};
        float ptv[4] = {pt.x, pt.y, pt.z, pt.w};
        hvv[0] = hv.x; hvv[1] = hv.y; hvv[2] = hv.z; hvv[3] = hv.w;
        #pragma unroll
        for (int jj = 0; jj < 4; jj++) {
            float cl = pfv[jj] + rf[jj];
            float e2 = __expf(2.f * cl);
            float cand = (e2 - 1.f) / (e2 + 1.f);
            float gate = 1.f / (1.f + __expf(-(pgv[jj] + rg[jj])));
            float tau  = 0.5f + 1.5f / (1.f + __expf(-(ptv[jj] + rt[jj])));
            float hn = hvv[jj] + (gate * cand - hvv[jj]) / tau;
            float e2h = __expf(2.f * hn);
            out[jj] = (e2h - 1.f) / (e2h + 1.f);
        }
        *(float4*)&hout[b * HID + hc] = make_float4(out[0], out[1], out[2], out[3]);
    }
}

// ---------------- head: [4096,256] x [256,10] + bias ----------------
__global__ void head_kernel(const float* __restrict__ hw,
                            const float* __restrict__ hb,
                            float* __restrict__ out)
{
    int gwarp = (blockIdx.x * blockDim.x + threadIdx.x) >> 5;
    int lane  = threadIdx.x & 31;
    if (gwarp >= BATCH * 10) return;
    int o = gwarp % 10;
    int b = gwarp / 10;
    const float* h = g_h[0];   // final state lands in buffer 0 after 64 steps
    float s = 0.f;
    #pragma unroll
    for (int k = lane; k < HID; k += 32)
        s += h[b * HID + k] * hw[o * HID + k];
    #pragma unroll
    for (int off = 16; off; off >>= 1)
        s += __shfl_down_sync(0xffffffffu, s, off);
    if (lane == 0) out[b * 10 + o] = s + hb[o];
}

extern "C" void kernel_launch(void* const* d_in, const int* in_sizes, int n_in,
                              void* d_out, int out_size)
{
    const float* x      = (const float*)d_in[0];
    const float* ffw    = (const float*)d_in[1];
    const float* ffb    = (const float*)d_in[2];
    const float* ffrw   = (const float*)d_in[3];
    const float* ffbias = (const float*)d_in[4];
    const float* gw     = (const float*)d_in[5];
    const float* gb     = (const float*)d_in[6];
    const float* grw    = (const float*)d_in[7];
    const float* gbias  = (const float*)d_in[8];
    const float* tw     = (const float*)d_in[9];
    const float* tb     = (const float*)d_in[10];
    const float* trw    = (const float*)d_in[11];
    const float* tbias  = (const float*)d_in[12];
    const float* hw     = (const float*)d_in[13];
    const float* hb     = (const float*)d_in[14];
    float* out = (float*)d_out;

    // h0 = 0 (must re-zero every call: deterministic replay)
    zero_h_kernel<<<(BATCH * HID + 255) / 256, 256>>>();

    // all input projections, batched over (t, b)
    dim3 pgrid((T * BATCH) / BM, HID / BN);
    proj_kernel<<<pgrid, 256>>>(x, ffw, ffb, ffbias, gw, gb, gbias, tw, tb, tbias);

    // 64 sequential LTC steps (ping-pong h buffers)
    dim3 sgrid(BATCH / BM, HID / BN);
    for (int t = 0; t < T; t++)
        step_kernel<<<sgrid, 256>>>(t, ffrw, grw, trw);

    // classifier head
    head_kernel<<<(BATCH * 10 * 32 + 255) / 256, 256>>>(hw, hb, out);
}

// round 6
// speedup vs baseline: 1.6172x; 1.3555x over previous
#include <cuda_runtime.h>
#include <cuda_bf16.h>
#include <math.h>
#include <cstdint>

#define BATCH 4096
#define T 64
#define HID 256
#define INDIM 192

// ---------------- device scratch ----------------
__device__ float g_proj[3][(size_t)T * BATCH * HID];              // input projections
__device__ float g_h[2][BATCH * HID];                             // fp32 h ping-pong
__device__ __nv_bfloat16 g_wbf[3][2][HID * HID];                  // W hi/lo bf16
__device__ __nv_bfloat16 g_hbf[2][2][(size_t)BATCH * HID];        // h hi/lo bf16 ping-pong

// ---------------- helpers ----------------
__device__ __forceinline__ uint32_t smem_to_u32(const void* p) {
    uint32_t a;
    asm("{ .reg .u64 t; cvta.to.shared.u64 t, %1; cvt.u32.u64 %0, t; }" : "=r"(a) : "l"(p));
    return a;
}
__device__ __forceinline__ uint32_t lds32(uint32_t a) {
    uint32_t v;
    asm volatile("ld.shared.b32 %0, [%1];" : "=r"(v) : "r"(a));
    return v;
}
#define CP_ASYNC16(dst, src) \
    asm volatile("cp.async.cg.shared.global [%0], [%1], 16;" :: "r"(dst), "l"(src))
#define CP_COMMIT() asm volatile("cp.async.commit_group;" ::: "memory")
#define CP_WAIT(n)  asm volatile("cp.async.wait_group %0;" :: "n"(n) : "memory")

// bf16 mma: D(16x8 fp32) += A(16x16) * B(16x8), A row-major frag, B col frag
__device__ __forceinline__ void mma_bf16(float* c, const uint32_t* a, const uint32_t* b) {
    asm volatile(
        "mma.sync.aligned.m16n8k16.row.col.f32.bf16.bf16.f32 "
        "{%0,%1,%2,%3}, {%4,%5,%6,%7}, {%8,%9}, {%0,%1,%2,%3};"
        : "+f"(c[0]), "+f"(c[1]), "+f"(c[2]), "+f"(c[3])
        : "r"(a[0]), "r"(a[1]), "r"(a[2]), "r"(a[3]), "r"(b[0]), "r"(b[1]));
}

// ---------------- packed fp32 helpers (proj kernel) ----------------
__device__ __forceinline__ void fma2(unsigned long long& d,
                                     unsigned long long a,
                                     unsigned long long b) {
    asm("fma.rn.f32x2 %0, %1, %2, %0;" : "+l"(d) : "l"(a), "l"(b));
}
__device__ __forceinline__ unsigned long long dup2(float x) {
    unsigned long long r;
    asm("mov.b64 %0, {%1, %1};" : "=l"(r) : "f"(x));
    return r;
}
__device__ __forceinline__ void unpack2(unsigned long long v, float& lo, float& hi) {
    asm("mov.b64 {%0, %1}, %2;" : "=f"(lo), "=f"(hi) : "l"(v));
}

// ---------------- zero h0 ----------------
__global__ void zero_h_kernel() {
    int i = blockIdx.x * blockDim.x + threadIdx.x;
    if (i < BATCH * HID) {
        g_h[0][i] = 0.f;
        g_hbf[0][0][i] = __float2bfloat16(0.f);
        g_hbf[0][1][i] = __float2bfloat16(0.f);
    }
}

// ---------------- W split prep: fp32 -> bf16 hi + lo ----------------
__global__ void wprep_kernel(const float* __restrict__ wf,
                             const float* __restrict__ wg,
                             const float* __restrict__ wt) {
    int i = blockIdx.x * blockDim.x + threadIdx.x;
    if (i >= HID * HID) return;
    const float* ws[3] = {wf, wg, wt};
    #pragma unroll
    for (int m = 0; m < 3; m++) {
        float x = ws[m][i];
        __nv_bfloat16 h = __float2bfloat16(x);
        g_wbf[m][0][i] = h;
        g_wbf[m][1][i] = __float2bfloat16(x - __bfloat162float(h));
    }
}

// =========================================================================
// proj kernel (R4: FFMA2 + double-buffer) — unchanged
// =========================================================================
#define BM 128
#define BN 64
#define BK 16

__global__ __launch_bounds__(256, 1) void proj_kernel(
    const float* __restrict__ x,
    const float* __restrict__ wf, const float* __restrict__ bfa, const float* __restrict__ bfb,
    const float* __restrict__ wg, const float* __restrict__ bga, const float* __restrict__ bgb,
    const float* __restrict__ wt, const float* __restrict__ bta, const float* __restrict__ btb)
{
    __shared__ __align__(16) float As[2][BK][BM + 4];
    __shared__ __align__(16) float Bf[2][BK][BN + 4];
    __shared__ __align__(16) float Bg[2][BK][BN + 4];
    __shared__ __align__(16) float Bt[2][BK][BN + 4];

    const int row0 = blockIdx.x * BM;
    const int col0 = blockIdx.y * BN;
    const int tid  = threadIdx.x;
    const int r  = tid >> 4;
    const int c  = tid & 15;
    const int ki = tid & 15;
    const int si = tid >> 4;

    const int t  = row0 / BATCH;
    const int b0 = row0 % BATCH;

    unsigned long long accf[8][2] = {};
    unsigned long long accg[8][2] = {};
    unsigned long long acct[8][2] = {};

    float aR[8], bRf[4], bRg[4], bRt[4];

    auto load_tile = [&](int k0) {
        const int i  = k0 + ki;
        const int ch = i >> 6;
        const int w  = i & 63;
        #pragma unroll
        for (int p = 0; p < 8; p++) {
            int bb = b0 + si + p * 16;
            aR[p] = x[(((bb * 3 + ch) << 6) + t) * 64 + w];
        }
        #pragma unroll
        for (int p = 0; p < 4; p++) {
            int j = col0 + si + p * 16;
            bRf[p] = wf[j * INDIM + i];
            bRg[p] = wg[j * INDIM + i];
            bRt[p] = wt[j * INDIM + i];
        }
    };
    auto sts_tile = [&](int buf) {
        #pragma unroll
        for (int p = 0; p < 8; p++) As[buf][ki][si + p * 16] = aR[p];
        #pragma unroll
        for (int p = 0; p < 4; p++) {
            Bf[buf][ki][si + p * 16] = bRf[p];
            Bg[buf][ki][si + p * 16] = bRg[p];
            Bt[buf][ki][si + p * 16] = bRt[p];
        }
    };

    const int NT = INDIM / BK;   // 12
    load_tile(0);
    sts_tile(0);
    __syncthreads();

    for (int kt = 0; kt < NT; kt++) {
        const int cur = kt & 1;
        if (kt + 1 < NT) load_tile((kt + 1) * BK);
        #pragma unroll
        for (int kk = 0; kk < BK; kk++) {
            float4 a0 = *(const float4*)&As[cur][kk][r * 8];
            float4 a1 = *(const float4*)&As[cur][kk][r * 8 + 4];
            ulonglong2 vf = *(const ulonglong2*)&Bf[cur][kk][c * 4];
            ulonglong2 vg = *(const ulonglong2*)&Bg[cur][kk][c * 4];
            ulonglong2 vt = *(const ulonglong2*)&Bt[cur][kk][c * 4];
            float av[8] = {a0.x, a0.y, a0.z, a0.w, a1.x, a1.y, a1.z, a1.w};
            #pragma unroll
            for (int ii = 0; ii < 8; ii++) {
                unsigned long long ad = dup2(av[ii]);
                fma2(accf[ii][0], ad, vf.x); fma2(accf[ii][1], ad, vf.y);
                fma2(accg[ii][0], ad, vg.x); fma2(accg[ii][1], ad, vg.y);
                fma2(acct[ii][0], ad, vt.x); fma2(acct[ii][1], ad, vt.y);
            }
        }
        if (kt + 1 < NT) {
            __syncthreads();
            sts_tile(cur ^ 1);
            __syncthreads();
        }
    }

    const int hc = col0 + c * 4;
    float4 biasf = make_float4(bfa[hc] + bfb[hc], bfa[hc+1] + bfb[hc+1],
                               bfa[hc+2] + bfb[hc+2], bfa[hc+3] + bfb[hc+3]);
    float4 biasg = make_float4(bga[hc] + bgb[hc], bga[hc+1] + bgb[hc+1],
                               bga[hc+2] + bgb[hc+2], bga[hc+3] + bgb[hc+3]);
    float4 biast = make_float4(bta[hc] + btb[hc], bta[hc+1] + btb[hc+1],
                               bta[hc+2] + btb[hc+2], bta[hc+3] + btb[hc+3]);
    #pragma unroll
    for (int ii = 0; ii < 8; ii++) {
        int b = b0 + r * 8 + ii;
        size_t base = ((size_t)t * BATCH + b) * HID + hc;
        float4 vfo, vgo, vto;
        unpack2(accf[ii][0], vfo.x, vfo.y); unpack2(accf[ii][1], vfo.z, vfo.w);
        unpack2(accg[ii][0], vgo.x, vgo.y); unpack2(accg[ii][1], vgo.z, vgo.w);
        unpack2(acct[ii][0], vto.x, vto.y); unpack2(acct[ii][1], vto.z, vto.w);
        vfo.x += biasf.x; vfo.y += biasf.y; vfo.z += biasf.z; vfo.w += biasf.w;
        vgo.x += biasg.x; vgo.y += biasg.y; vgo.z += biasg.z; vgo.w += biasg.w;
        vto.x += biast.x; vto.y += biast.y; vto.z += biast.z; vto.w += biast.w;
        *(float4*)&g_proj[0][base] = vfo;
        *(float4*)&g_proj[1][base] = vgo;
        *(float4*)&g_proj[2][base] = vto;
    }
}

// =========================================================================
// recurrent step via mma.sync bf16 split-precision
// CTA: 128 batch rows x 64 out cols, 8 warps; warp w: rows (w&3)*32, cols (w>>2)*32
// smem double buffer: per buf: A (2 splits x 128 rows x 64k, pitch 72) = 36864B
//                              B (6 regions x 64 rows x 64k, pitch 72) = 55296B
// =========================================================================
#define KCHUNK 64
#define PITCHB 144                    // (64+8) bf16 * 2B, conflict-free for frag loads
#define A_BYTES (256 * PITCHB)        // 36864
#define B_BYTES (384 * PITCHB)        // 55296
#define BUF_BYTES (A_BYTES + B_BYTES) // 92160
#define STEP_SMEM (2 * BUF_BYTES)     // 184320

__global__ __launch_bounds__(256, 1) void step_mma_kernel(int t)
{
    extern __shared__ char sm[];
    const uint32_t sbase = smem_to_u32(sm);

    const float* __restrict__ hin = g_h[t & 1];
    float* __restrict__ hout      = g_h[(t + 1) & 1];
    const __nv_bfloat16* __restrict__ hbf_hi = g_hbf[t & 1][0];
    const __nv_bfloat16* __restrict__ hbf_lo = g_hbf[t & 1][1];

    const int tid   = threadIdx.x;
    const int warp  = tid >> 5;
    const int lane  = tid & 31;
    const int group = lane >> 2;
    const int tig   = lane & 3;
    const int b0    = blockIdx.x * 128;
    const int n0    = blockIdx.y * 64;
    const int m0w   = (warp & 3) * 32;
    const int n0w   = (warp >> 2) * 32;

    float acc[3][2][4][4] = {};   // [mat][mfrag][nfrag][reg]

    // ---- async staging of one K chunk into buffer bb ----
    auto stage = [&](int chunk, int bb) {
        const int kc0 = chunk * KCHUNK;
        const uint32_t dstb = sbase + bb * BUF_BYTES;
        // A: 2048 16B units (2 splits x 128 rows x 8 kb)
        #pragma unroll
        for (int j = 0; j < 8; j++) {
            int u = tid + j * 256;
            int s = u >> 10, row = (u >> 3) & 127, kb = u & 7;
            const __nv_bfloat16* src =
                (s == 0 ? hbf_hi : hbf_lo) + (size_t)(b0 + row) * HID + kc0 + kb * 8;
            uint32_t dst = dstb + (uint32_t)((s * 128 + row) * PITCHB + kb * 16);
            CP_ASYNC16(dst, src);
        }
        // B: 3072 16B units (6 regions x 64 rows x 8 kb)
        #pragma unroll
        for (int j = 0; j < 12; j++) {
            int u = tid + j * 256;
            int rg = u >> 9, row = (u >> 3) & 63, kb = u & 7;
            int mat = rg >> 1, sp = rg & 1;
            const __nv_bfloat16* src =
                &g_wbf[mat][sp][(size_t)(n0 + row) * HID + kc0 + kb * 8];
            uint32_t dst = dstb + A_BYTES + (uint32_t)((rg * 64 + row) * PITCHB + kb * 16);
            CP_ASYNC16(dst, src);
        }
    };

    // ---- compute one staged chunk ----
    auto compute = [&](int bb) {
        const uint32_t Abase = sbase + bb * BUF_BYTES;
        const uint32_t Bbase = Abase + A_BYTES;
        #pragma unroll
        for (int q = 0; q < 4; q++) {          // 4 k16 steps per chunk
            const uint32_t koff = q * 32 + tig * 4;
            uint32_t ahi[2][4], alo[2][4];
            #pragma unroll
            for (int f = 0; f < 2; f++) {
                uint32_t rh = Abase + (uint32_t)((m0w + f * 16 + group) * PITCHB) + koff;
                ahi[f][0] = lds32(rh);
                ahi[f][1] = lds32(rh + 8 * PITCHB);
                ahi[f][2] = lds32(rh + 16);
                ahi[f][3] = lds32(rh + 8 * PITCHB + 16);
                uint32_t rl = rh + 128 * PITCHB;
                alo[f][0] = lds32(rl);
                alo[f][1] = lds32(rl + 8 * PITCHB);
                alo[f][2] = lds32(rl + 16);
                alo[f][3] = lds32(rl + 8 * PITCHB + 16);
            }
            #pragma unroll
            for (int mat = 0; mat < 3; mat++) {
                #pragma unroll
                for (int j = 0; j < 4; j++) {
                    uint32_t rbh = Bbase +
                        (uint32_t)(((mat * 2) * 64 + n0w + j * 8 + group) * PITCHB) + koff;
                    uint32_t bh[2] = {lds32(rbh), lds32(rbh + 16)};
                    uint32_t rbl = rbh + 64 * PITCHB;
                    uint32_t bl[2] = {lds32(rbl), lds32(rbl + 16)};
                    #pragma unroll
                    for (int f = 0; f < 2; f++) {
                        mma_bf16(acc[mat][f][j], ahi[f], bh);
                        mma_bf16(acc[mat][f][j], ahi[f], bl);
                        mma_bf16(acc[mat][f][j], alo[f], bh);
                    }
                }
            }
        }
    };

    stage(0, 0);
    CP_COMMIT();
    #pragma unroll 1
    for (int c = 0; c < 4; c++) {
        if (c < 3) {
            stage(c + 1, (c + 1) & 1);
            CP_COMMIT();
            CP_WAIT(1);
        } else {
            CP_WAIT(0);
        }
        __syncthreads();
        compute(c & 1);
        __syncthreads();
    }

    // ---- fused LTC epilogue from accumulator fragments ----
    #pragma unroll
    for (int f = 0; f < 2; f++) {
        #pragma unroll
        for (int hh = 0; hh < 2; hh++) {
            const int m = m0w + f * 16 + group + hh * 8;
            const int b = b0 + m;
            const size_t hrow  = (size_t)b * HID;
            const size_t pbase = ((size_t)t * BATCH + b) * HID;
            #pragma unroll
            for (int j = 0; j < 4; j++) {
                const int jabs = n0 + n0w + j * 8 + tig * 2;
                float2 pf = *(const float2*)&g_proj[0][pbase + jabs];
                float2 pg = *(const float2*)&g_proj[1][pbase + jabs];
                float2 pt = *(const float2*)&g_proj[2][pbase + jabs];
                float2 hv = *(const float2*)&hin[hrow + jabs];
                float o2[2];
                #pragma unroll
                for (int e = 0; e < 2; e++) {
                    float rf = acc[0][f][j][hh * 2 + e];
                    float rg = acc[1][f][j][hh * 2 + e];
                    float rt = acc[2][f][j][hh * 2 + e];
                    float pfe = e ? pf.y : pf.x;
                    float pge = e ? pg.y : pg.x;
                    float pte = e ? pt.y : pt.x;
                    float hve = e ? hv.y : hv.x;
                    float e2 = __expf(2.f * (pfe + rf));
                    float cand = (e2 - 1.f) / (e2 + 1.f);
                    float gate = 1.f / (1.f + __expf(-(pge + rg)));
                    float tau  = 0.5f + 1.5f / (1.f + __expf(-(pte + rt)));
                    float hn = hve + (gate * cand - hve) / tau;
                    float e2h = __expf(2.f * hn);
                    o2[e] = (e2h - 1.f) / (e2h + 1.f);
                }
                *(float2*)&hout[hrow + jabs] = make_float2(o2[0], o2[1]);
                // bf16 hi/lo split for next step's A operand
                __nv_bfloat16 h0 = __float2bfloat16(o2[0]);
                __nv_bfloat16 h1 = __float2bfloat16(o2[1]);
                __nv_bfloat162 hhp = __halves2bfloat162(h0, h1);
                __nv_bfloat162 llp = __halves2bfloat162(
                    __float2bfloat16(o2[0] - __bfloat162float(h0)),
                    __float2bfloat16(o2[1] - __bfloat162float(h1)));
                *(uint32_t*)&g_hbf[(t + 1) & 1][0][hrow + jabs] = *(uint32_t*)&hhp;
                *(uint32_t*)&g_hbf[(t + 1) & 1][1][hrow + jabs] = *(uint32_t*)&llp;
            }
        }
    }
}

// ---------------- head: [4096,256] x [256,10] + bias ----------------
__global__ void head_kernel(const float* __restrict__ hw,
                            const float* __restrict__ hb,
                            float* __restrict__ out)
{
    int gwarp = (blockIdx.x * blockDim.x + threadIdx.x) >> 5;
    int lane  = threadIdx.x & 31;
    if (gwarp >= BATCH * 10) return;
    int o = gwarp % 10;
    int b = gwarp / 10;
    const float* h = g_h[0];   // T=64 even -> final state in buffer 0
    float s = 0.f;
    #pragma unroll
    for (int k = lane; k < HID; k += 32)
        s += h[b * HID + k] * hw[o * HID + k];
    #pragma unroll
    for (int off = 16; off; off >>= 1)
        s += __shfl_down_sync(0xffffffffu, s, off);
    if (lane == 0) out[b * 10 + o] = s + hb[o];
}

extern "C" void kernel_launch(void* const* d_in, const int* in_sizes, int n_in,
                              void* d_out, int out_size)
{
    const float* x      = (const float*)d_in[0];
    const float* ffw    = (const float*)d_in[1];
    const float* ffb    = (const float*)d_in[2];
    const float* ffrw   = (const float*)d_in[3];
    const float* ffbias = (const float*)d_in[4];
    const float* gw     = (const float*)d_in[5];
    const float* gb     = (const float*)d_in[6];
    const float* grw    = (const float*)d_in[7];
    const float* gbias  = (const float*)d_in[8];
    const float* tw     = (const float*)d_in[9];
    const float* tb     = (const float*)d_in[10];
    const float* trw    = (const float*)d_in[11];
    const float* tbias  = (const float*)d_in[12];
    const float* hw     = (const float*)d_in[13];
    const float* hb     = (const float*)d_in[14];
    float* out = (float*)d_out;

    cudaFuncSetAttribute(step_mma_kernel,
                         cudaFuncAttributeMaxDynamicSharedMemorySize, STEP_SMEM);

    // h0 = 0 (fp32 + bf16 hi/lo)
    zero_h_kernel<<<(BATCH * HID + 255) / 256, 256>>>();

    // W -> bf16 hi/lo scratch
    wprep_kernel<<<(HID * HID + 255) / 256, 256>>>(ffrw, grw, trw);

    // all input projections, batched over (t, b)
    dim3 pgrid((T * BATCH) / BM, HID / BN);
    proj_kernel<<<pgrid, 256>>>(x, ffw, ffb, ffbias, gw, gb, gbias, tw, tb, tbias);

    // 64 sequential LTC steps on the tensor pipe (ping-pong h buffers)
    dim3 sgrid(BATCH / 128, HID / 64);
    for (int t = 0; t < T; t++)
        step_mma_kernel<<<sgrid, 256, STEP_SMEM>>>(t);

    // classifier head
    head_kernel<<<(BATCH * 10 * 32 + 255) / 256, 256>>>(hw, hb, out);
}

// round 7
// speedup vs baseline: 2.1657x; 1.3392x over previous
#include <cuda_runtime.h>
#include <cuda_bf16.h>
#include <math.h>
#include <cstdint>

#define BATCH 4096
#define T 64
#define HID 256
#define INDIM 192

// ---------------- device scratch ----------------
__device__ float g_proj[3][(size_t)T * BATCH * HID];              // input projections
__device__ float g_h[2][BATCH * HID];                             // fp32 h ping-pong
__device__ __nv_bfloat16 g_wbf[3][2][HID * HID];                  // W_rec hi/lo bf16
__device__ __nv_bfloat16 g_wbf_in[3][2][HID * INDIM];             // W_in hi/lo bf16
__device__ __nv_bfloat16 g_hbf[2][2][(size_t)BATCH * HID];        // h hi/lo bf16 ping-pong

// ---------------- helpers ----------------
__device__ __forceinline__ uint32_t smem_to_u32(const void* p) {
    uint32_t a;
    asm("{ .reg .u64 t; cvta.to.shared.u64 t, %1; cvt.u32.u64 %0, t; }" : "=r"(a) : "l"(p));
    return a;
}
__device__ __forceinline__ uint32_t lds32(uint32_t a) {
    uint32_t v;
    asm volatile("ld.shared.b32 %0, [%1];" : "=r"(v) : "r"(a));
    return v;
}
__device__ __forceinline__ void sts64(uint32_t a, uint32_t v0, uint32_t v1) {
    asm volatile("st.shared.v2.b32 [%0], {%1, %2};" :: "r"(a), "r"(v0), "r"(v1));
}
#define CP_ASYNC16(dst, src) \
    asm volatile("cp.async.cg.shared.global [%0], [%1], 16;" :: "r"(dst), "l"(src))
#define CP_COMMIT() asm volatile("cp.async.commit_group;" ::: "memory")
#define CP_WAIT(n)  asm volatile("cp.async.wait_group %0;" :: "n"(n) : "memory")

// bf16 mma: D(16x8 fp32) += A(16x16) * B(16x8)
__device__ __forceinline__ void mma_bf16(float* c, const uint32_t* a, const uint32_t* b) {
    asm volatile(
        "mma.sync.aligned.m16n8k16.row.col.f32.bf16.bf16.f32 "
        "{%0,%1,%2,%3}, {%4,%5,%6,%7}, {%8,%9}, {%0,%1,%2,%3};"
        : "+f"(c[0]), "+f"(c[1]), "+f"(c[2]), "+f"(c[3])
        : "r"(a[0]), "r"(a[1]), "r"(a[2]), "r"(a[3]), "r"(b[0]), "r"(b[1]));
}

__device__ __forceinline__ uint32_t pack_hi2(float x0, float x1) {
    __nv_bfloat162 h = __halves2bfloat162(__float2bfloat16(x0), __float2bfloat16(x1));
    return *(uint32_t*)&h;
}
__device__ __forceinline__ uint32_t pack_lo2(float x0, float x1) {
    __nv_bfloat16 h0 = __float2bfloat16(x0);
    __nv_bfloat16 h1 = __float2bfloat16(x1);
    __nv_bfloat162 l = __halves2bfloat162(
        __float2bfloat16(x0 - __bfloat162float(h0)),
        __float2bfloat16(x1 - __bfloat162float(h1)));
    return *(uint32_t*)&l;
}

// ---------------- zero h0 ----------------
__global__ void zero_h_kernel() {
    int i = blockIdx.x * blockDim.x + threadIdx.x;
    if (i < BATCH * HID) {
        g_h[0][i] = 0.f;
        g_hbf[0][0][i] = __float2bfloat16(0.f);
        g_hbf[0][1][i] = __float2bfloat16(0.f);
    }
}

// ---------------- W split prep: fp32 -> bf16 hi + lo (recurrent + input) ----------------
__global__ void wprep_kernel(const float* __restrict__ wfr, const float* __restrict__ wgr,
                             const float* __restrict__ wtr,
                             const float* __restrict__ wfi, const float* __restrict__ wgi,
                             const float* __restrict__ wti) {
    int i = blockIdx.x * blockDim.x + threadIdx.x;
    if (i < HID * HID) {
        const float* ws[3] = {wfr, wgr, wtr};
        #pragma unroll
        for (int m = 0; m < 3; m++) {
            float x = ws[m][i];
            __nv_bfloat16 h = __float2bfloat16(x);
            g_wbf[m][0][i] = h;
            g_wbf[m][1][i] = __float2bfloat16(x - __bfloat162float(h));
        }
    }
    if (i < HID * INDIM) {
        const float* ws[3] = {wfi, wgi, wti};
        #pragma unroll
        for (int m = 0; m < 3; m++) {
            float x = ws[m][i];
            __nv_bfloat16 h = __float2bfloat16(x);
            g_wbf_in[m][0][i] = h;
            g_wbf_in[m][1][i] = __float2bfloat16(x - __bfloat162float(h));
        }
    }
}

// ---------------- shared tiling for both mma kernels ----------------
#define PITCHB 144                    // (64+8) bf16 * 2B, conflict-free
#define A_BYTES (256 * PITCHB)        // 2 splits x 128 rows
#define B_BYTES (384 * PITCHB)        // 6 regions x 64 rows
#define BUF_BYTES (A_BYTES + B_BYTES) // 92160
#define STEP_SMEM (2 * BUF_BYTES)     // 184320

// Compute one staged 64-wide K chunk. Product-outer ordering: same-acc reuse
// distance = 8 MMAs (covers HMMA latency at low occupancy).
#define COMPUTE_CHUNK(bb)                                                        \
    do {                                                                         \
        const uint32_t Abase = sbase + (bb) * BUF_BYTES;                         \
        const uint32_t Bbase = Abase + A_BYTES;                                  \
        _Pragma("unroll")                                                        \
        for (int q = 0; q < 4; q++) {                                            \
            const uint32_t koff = q * 32 + tig * 4;                              \
            uint32_t ahi[2][4], alo[2][4];                                       \
            _Pragma("unroll")                                                    \
            for (int f = 0; f < 2; f++) {                                        \
                uint32_t rh = Abase + (uint32_t)((m0w + f * 16 + group) * PITCHB) + koff; \
                ahi[f][0] = lds32(rh);                                           \
                ahi[f][1] = lds32(rh + 8 * PITCHB);                              \
                ahi[f][2] = lds32(rh + 16);                                      \
                ahi[f][3] = lds32(rh + 8 * PITCHB + 16);                         \
                uint32_t rl = rh + 128 * PITCHB;                                 \
                alo[f][0] = lds32(rl);                                           \
                alo[f][1] = lds32(rl + 8 * PITCHB);                              \
                alo[f][2] = lds32(rl + 16);                                      \
                alo[f][3] = lds32(rl + 8 * PITCHB + 16);                         \
            }                                                                    \
            _Pragma("unroll")                                                    \
            for (int mat = 0; mat < 3; mat++) {                                  \
                uint32_t bh[4][2], bl[4][2];                                     \
                _Pragma("unroll")                                                \
                for (int j = 0; j < 4; j++) {                                    \
                    uint32_t rbh = Bbase +                                       \
                        (uint32_t)(((mat * 2) * 64 + n0w + j * 8 + group) * PITCHB) + koff; \
                    bh[j][0] = lds32(rbh); bh[j][1] = lds32(rbh + 16);           \
                    uint32_t rbl = rbh + 64 * PITCHB;                            \
                    bl[j][0] = lds32(rbl); bl[j][1] = lds32(rbl + 16);           \
                }                                                                \
                _Pragma("unroll")                                                \
                for (int j = 0; j < 4; j++)                                      \
                    { mma_bf16(acc[mat][0][j], ahi[0], bh[j]);                   \
                      mma_bf16(acc[mat][1][j], ahi[1], bh[j]); }                 \
                _Pragma("unroll")                                                \
                for (int j = 0; j < 4; j++)                                      \
                    { mma_bf16(acc[mat][0][j], ahi[0], bl[j]);                   \
                      mma_bf16(acc[mat][1][j], ahi[1], bl[j]); }                 \
                _Pragma("unroll")                                                \
                for (int j = 0; j < 4; j++)                                      \
                    { mma_bf16(acc[mat][0][j], alo[0], bh[j]);                   \
                      mma_bf16(acc[mat][1][j], alo[1], bh[j]); }                 \
            }                                                                    \
        }                                                                        \
    } while (0)

// =========================================================================
// proj kernel via mma.sync: rows m = t*4096+b, K=192 (3 chunks), 64 cols x 3 mats
// grid (2048, 4), 256 threads
// =========================================================================
__global__ __launch_bounds__(256, 1) void proj_mma_kernel(
    const float* __restrict__ x,
    const float* __restrict__ bfa, const float* __restrict__ bfb,
    const float* __restrict__ bga, const float* __restrict__ bgb,
    const float* __restrict__ bta, const float* __restrict__ btb)
{
    extern __shared__ char sm[];
    const uint32_t sbase = smem_to_u32(sm);

    const int tid   = threadIdx.x;
    const int warp  = tid >> 5;
    const int lane  = tid & 31;
    const int group = lane >> 2;
    const int tig   = lane & 3;
    const int m0    = blockIdx.x * 128;
    const int n0    = blockIdx.y * 64;
    const int m0w   = (warp & 3) * 32;
    const int n0w   = (warp >> 2) * 32;
    const int tq    = m0 >> 12;          // time index (4096 rows per t)
    const int bq0   = m0 & 4095;         // batch base

    float acc[3][2][4][4] = {};

    // stage A: gather x fp32, split to bf16 hi/lo in smem
    auto stageA = [&](int chunk, int bb) {
        const uint32_t dstb = sbase + bb * BUF_BYTES;
        #pragma unroll
        for (int j = 0; j < 8; j++) {
            int u   = tid + j * 256;       // 0..2047 float4 units
            int row = u >> 4;
            int f4  = u & 15;
            float4 v = *(const float4*)&x[((((size_t)(bq0 + row) * 3 + chunk) << 6) + tq) * 64 + f4 * 4];
            uint32_t base = dstb + (uint32_t)(row * PITCHB + f4 * 8);
            sts64(base, pack_hi2(v.x, v.y), pack_hi2(v.z, v.w));
            sts64(base + 128 * PITCHB, pack_lo2(v.x, v.y), pack_lo2(v.z, v.w));
        }
    };
    // stage B: cp.async W_in hi/lo tiles
    auto stageB = [&](int chunk, int bb) {
        const int kc0 = chunk * 64;
        const uint32_t dstb = sbase + bb * BUF_BYTES + A_BYTES;
        #pragma unroll
        for (int j = 0; j < 12; j++) {
            int u = tid + j * 256;
            int rg = u >> 9, row = (u >> 3) & 63, kb = u & 7;
            int mat = rg >> 1, sp = rg & 1;
            const __nv_bfloat16* src =
                &g_wbf_in[mat][sp][(size_t)(n0 + row) * INDIM + kc0 + kb * 8];
            uint32_t dst = dstb + (uint32_t)((rg * 64 + row) * PITCHB + kb * 16);
            CP_ASYNC16(dst, src);
        }
    };

    stageB(0, 0); CP_COMMIT();
    stageA(0, 0);
    #pragma unroll 1
    for (int c = 0; c < 3; c++) {
        if (c < 2) {
            stageB(c + 1, (c + 1) & 1); CP_COMMIT();
            stageA(c + 1, (c + 1) & 1);
            CP_WAIT(1);
        } else {
            CP_WAIT(0);
        }
        __syncthreads();
        COMPUTE_CHUNK(c & 1);
        __syncthreads();
    }

    // epilogue: add biases, write g_proj
    const float* inb[3]  = {bfa, bga, bta};
    const float* hbb[3]  = {bfb, bgb, btb};
    #pragma unroll
    for (int f = 0; f < 2; f++) {
        #pragma unroll
        for (int hh = 0; hh < 2; hh++) {
            const int m = m0w + f * 16 + group + hh * 8;
            const size_t obase = (size_t)(m0 + m) * HID;
            #pragma unroll
            for (int j = 0; j < 4; j++) {
                const int jabs = n0 + n0w + j * 8 + tig * 2;
                #pragma unroll
                for (int mat = 0; mat < 3; mat++) {
                    float2 bi = *(const float2*)&inb[mat][jabs];
                    float2 bh2 = *(const float2*)&hbb[mat][jabs];
                    float2 o;
                    o.x = acc[mat][f][j][hh * 2]     + bi.x + bh2.x;
                    o.y = acc[mat][f][j][hh * 2 + 1] + bi.y + bh2.y;
                    *(float2*)&g_proj[mat][obase + jabs] = o;
                }
            }
        }
    }
}

// =========================================================================
// recurrent step via mma.sync bf16 split-precision (reordered MMAs)
// =========================================================================
__global__ __launch_bounds__(256, 1) void step_mma_kernel(int t)
{
    extern __shared__ char sm[];
    const uint32_t sbase = smem_to_u32(sm);

    const float* __restrict__ hin = g_h[t & 1];
    float* __restrict__ hout      = g_h[(t + 1) & 1];
    const __nv_bfloat16* __restrict__ hbf_hi = g_hbf[t & 1][0];
    const __nv_bfloat16* __restrict__ hbf_lo = g_hbf[t & 1][1];

    const int tid   = threadIdx.x;
    const int warp  = tid >> 5;
    const int lane  = tid & 31;
    const int group = lane >> 2;
    const int tig   = lane & 3;
    const int b0    = blockIdx.x * 128;
    const int n0    = blockIdx.y * 64;
    const int m0w   = (warp & 3) * 32;
    const int n0w   = (warp >> 2) * 32;

    float acc[3][2][4][4] = {};

    auto stage = [&](int chunk, int bb) {
        const int kc0 = chunk * 64;
        const uint32_t dstb = sbase + bb * BUF_BYTES;
        #pragma unroll
        for (int j = 0; j < 8; j++) {
            int u = tid + j * 256;
            int s = u >> 10, row = (u >> 3) & 127, kb = u & 7;
            const __nv_bfloat16* src =
                (s == 0 ? hbf_hi : hbf_lo) + (size_t)(b0 + row) * HID + kc0 + kb * 8;
            uint32_t dst = dstb + (uint32_t)((s * 128 + row) * PITCHB + kb * 16);
            CP_ASYNC16(dst, src);
        }
        #pragma unroll
        for (int j = 0; j < 12; j++) {
            int u = tid + j * 256;
            int rg = u >> 9, row = (u >> 3) & 63, kb = u & 7;
            int mat = rg >> 1, sp = rg & 1;
            const __nv_bfloat16* src =
                &g_wbf[mat][sp][(size_t)(n0 + row) * HID + kc0 + kb * 8];
            uint32_t dst = dstb + A_BYTES + (uint32_t)((rg * 64 + row) * PITCHB + kb * 16);
            CP_ASYNC16(dst, src);
        }
    };

    stage(0, 0);
    CP_COMMIT();
    #pragma unroll 1
    for (int c = 0; c < 4; c++) {
        if (c < 3) {
            stage(c + 1, (c + 1) & 1);
            CP_COMMIT();
            CP_WAIT(1);
        } else {
            CP_WAIT(0);
        }
        __syncthreads();
        COMPUTE_CHUNK(c & 1);
        __syncthreads();
    }

    // ---- fused LTC epilogue from accumulator fragments ----
    #pragma unroll
    for (int f = 0; f < 2; f++) {
        #pragma unroll
        for (int hh = 0; hh < 2; hh++) {
            const int m = m0w + f * 16 + group + hh * 8;
            const int b = b0 + m;
            const size_t hrow  = (size_t)b * HID;
            const size_t pbase = ((size_t)t * BATCH + b) * HID;
            #pragma unroll
            for (int j = 0; j < 4; j++) {
                const int jabs = n0 + n0w + j * 8 + tig * 2;
                float2 pf = *(const float2*)&g_proj[0][pbase + jabs];
                float2 pg = *(const float2*)&g_proj[1][pbase + jabs];
                float2 pt = *(const float2*)&g_proj[2][pbase + jabs];
                float2 hv = *(const float2*)&hin[hrow + jabs];
                float o2[2];
                #pragma unroll
                for (int e = 0; e < 2; e++) {
                    float rf = acc[0][f][j][hh * 2 + e];
                    float rg = acc[1][f][j][hh * 2 + e];
                    float rt = acc[2][f][j][hh * 2 + e];
                    float pfe = e ? pf.y : pf.x;
                    float pge = e ? pg.y : pg.x;
                    float pte = e ? pt.y : pt.x;
                    float hve = e ? hv.y : hv.x;
                    float e2 = __expf(2.f * (pfe + rf));
                    float cand = (e2 - 1.f) / (e2 + 1.f);
                    float gate = 1.f / (1.f + __expf(-(pge + rg)));
                    float tau  = 0.5f + 1.5f / (1.f + __expf(-(pte + rt)));
                    float hn = hve + (gate * cand - hve) / tau;
                    float e2h = __expf(2.f * hn);
                    o2[e] = (e2h - 1.f) / (e2h + 1.f);
                }
                *(float2*)&hout[hrow + jabs] = make_float2(o2[0], o2[1]);
                *(uint32_t*)&g_hbf[(t + 1) & 1][0][hrow + jabs] = pack_hi2(o2[0], o2[1]);
                *(uint32_t*)&g_hbf[(t + 1) & 1][1][hrow + jabs] = pack_lo2(o2[0], o2[1]);
            }
        }
    }
}

// ---------------- head: [4096,256] x [256,10] + bias ----------------
__global__ void head_kernel(const float* __restrict__ hw,
                            const float* __restrict__ hb,
                            float* __restrict__ out)
{
    int gwarp = (blockIdx.x * blockDim.x + threadIdx.x) >> 5;
    int lane  = threadIdx.x & 31;
    if (gwarp >= BATCH * 10) return;
    int o = gwarp % 10;
    int b = gwarp / 10;
    const float* h = g_h[0];   // T=64 even -> final state in buffer 0
    float s = 0.f;
    #pragma unroll
    for (int k = lane; k < HID; k += 32)
        s += h[b * HID + k] * hw[o * HID + k];
    #pragma unroll
    for (int off = 16; off; off >>= 1)
        s += __shfl_down_sync(0xffffffffu, s, off);
    if (lane == 0) out[b * 10 + o] = s + hb[o];
}

extern "C" void kernel_launch(void* const* d_in, const int* in_sizes, int n_in,
                              void* d_out, int out_size)
{
    const float* x      = (const float*)d_in[0];
    const float* ffw    = (const float*)d_in[1];
    const float* ffb    = (const float*)d_in[2];
    const float* ffrw   = (const float*)d_in[3];
    const float* ffbias = (const float*)d_in[4];
    const float* gw     = (const float*)d_in[5];
    const float* gb     = (const float*)d_in[6];
    const float* grw    = (const float*)d_in[7];
    const float* gbias  = (const float*)d_in[8];
    const float* tw     = (const float*)d_in[9];
    const float* tb     = (const float*)d_in[10];
    const float* trw    = (const float*)d_in[11];
    const float* tbias  = (const float*)d_in[12];
    const float* hw     = (const float*)d_in[13];
    const float* hb     = (const float*)d_in[14];
    float* out = (float*)d_out;

    cudaFuncSetAttribute(step_mma_kernel,
                         cudaFuncAttributeMaxDynamicSharedMemorySize, STEP_SMEM);
    cudaFuncSetAttribute(proj_mma_kernel,
                         cudaFuncAttributeMaxDynamicSharedMemorySize, STEP_SMEM);

    // h0 = 0 (fp32 + bf16 hi/lo)
    zero_h_kernel<<<(BATCH * HID + 255) / 256, 256>>>();

    // W (recurrent + input) -> bf16 hi/lo scratch
    wprep_kernel<<<(HID * HID + 255) / 256, 256>>>(ffrw, grw, trw, ffw, gw, tw);

    // all input projections on the tensor pipe
    dim3 pgrid((T * BATCH) / 128, HID / 64);
    proj_mma_kernel<<<pgrid, 256, STEP_SMEM>>>(x, ffb, ffbias, gb, gbias, tb, tbias);

    // 64 sequential LTC steps on the tensor pipe (ping-pong h buffers)
    dim3 sgrid(BATCH / 128, HID / 64);
    for (int t = 0; t < T; t++)
        step_mma_kernel<<<sgrid, 256, STEP_SMEM>>>(t);

    // classifier head
    head_kernel<<<(BATCH * 10 * 32 + 255) / 256, 256>>>(hw, hb, out);
}

// round 8
// speedup vs baseline: 2.4921x; 1.1507x over previous
#include <cuda_runtime.h>
#include <cuda_bf16.h>
#include <math.h>
#include <cstdint>

#define BATCH 4096
#define T 64
#define HID 256
#define INDIM 192

// ---------------- device scratch ----------------
__device__ float g_proj[3][(size_t)T * BATCH * HID];              // input projections
__device__ float g_h[2][BATCH * HID];                             // fp32 h ping-pong
__device__ __nv_bfloat16 g_wbf[3][2][HID * HID];                  // W_rec hi/lo bf16
__device__ __nv_bfloat16 g_wbf_in[3][2][HID * INDIM];             // W_in hi/lo bf16
__device__ __nv_bfloat16 g_hbf[2][2][(size_t)BATCH * HID];        // h hi/lo bf16 ping-pong

// ---------------- helpers ----------------
__device__ __forceinline__ uint32_t smem_to_u32(const void* p) {
    uint32_t a;
    asm("{ .reg .u64 t; cvta.to.shared.u64 t, %1; cvt.u32.u64 %0, t; }" : "=r"(a) : "l"(p));
    return a;
}
__device__ __forceinline__ uint32_t lds32(uint32_t a) {
    uint32_t v;
    asm volatile("ld.shared.b32 %0, [%1];" : "=r"(v) : "r"(a));
    return v;
}
__device__ __forceinline__ void sts64(uint32_t a, uint32_t v0, uint32_t v1) {
    asm volatile("st.shared.v2.b32 [%0], {%1, %2};" :: "r"(a), "r"(v0), "r"(v1));
}
#define CP_ASYNC16(dst, src) \
    asm volatile("cp.async.cg.shared.global [%0], [%1], 16;" :: "r"(dst), "l"(src))
#define CP_COMMIT() asm volatile("cp.async.commit_group;" ::: "memory")
#define CP_WAIT(n)  asm volatile("cp.async.wait_group %0;" :: "n"(n) : "memory")

// bf16 mma: D(16x8 fp32) += A(16x16) * B(16x8)
__device__ __forceinline__ void mma_bf16(float* c, const uint32_t* a, const uint32_t* b) {
    asm volatile(
        "mma.sync.aligned.m16n8k16.row.col.f32.bf16.bf16.f32 "
        "{%0,%1,%2,%3}, {%4,%5,%6,%7}, {%8,%9}, {%0,%1,%2,%3};"
        : "+f"(c[0]), "+f"(c[1]), "+f"(c[2]), "+f"(c[3])
        : "r"(a[0]), "r"(a[1]), "r"(a[2]), "r"(a[3]), "r"(b[0]), "r"(b[1]));
}

__device__ __forceinline__ uint32_t pack_hi2(float x0, float x1) {
    __nv_bfloat162 h = __halves2bfloat162(__float2bfloat16(x0), __float2bfloat16(x1));
    return *(uint32_t*)&h;
}
__device__ __forceinline__ uint32_t pack_lo2(float x0, float x1) {
    __nv_bfloat16 h0 = __float2bfloat16(x0);
    __nv_bfloat16 h1 = __float2bfloat16(x1);
    __nv_bfloat162 l = __halves2bfloat162(
        __float2bfloat16(x0 - __bfloat162float(h0)),
        __float2bfloat16(x1 - __bfloat162float(h1)));
    return *(uint32_t*)&l;
}

// ---------------- zero h0 ----------------
__global__ void zero_h_kernel() {
    int i = blockIdx.x * blockDim.x + threadIdx.x;
    if (i < BATCH * HID) {
        g_h[0][i] = 0.f;
        g_hbf[0][0][i] = __float2bfloat16(0.f);
        g_hbf[0][1][i] = __float2bfloat16(0.f);
    }
}

// ---------------- W split prep: fp32 -> bf16 hi + lo ----------------
__global__ void wprep_kernel(const float* __restrict__ wfr, const float* __restrict__ wgr,
                             const float* __restrict__ wtr,
                             const float* __restrict__ wfi, const float* __restrict__ wgi,
                             const float* __restrict__ wti) {
    int i = blockIdx.x * blockDim.x + threadIdx.x;
    if (i < HID * HID) {
        const float* ws[3] = {wfr, wgr, wtr};
        #pragma unroll
        for (int m = 0; m < 3; m++) {
            float x = ws[m][i];
            __nv_bfloat16 h = __float2bfloat16(x);
            g_wbf[m][0][i] = h;
            g_wbf[m][1][i] = __float2bfloat16(x - __bfloat162float(h));
        }
    }
    if (i < HID * INDIM) {
        const float* ws[3] = {wfi, wgi, wti};
        #pragma unroll
        for (int m = 0; m < 3; m++) {
            float x = ws[m][i];
            __nv_bfloat16 h = __float2bfloat16(x);
            g_wbf_in[m][0][i] = h;
            g_wbf_in[m][1][i] = __float2bfloat16(x - __bfloat162float(h));
        }
    }
}

// ---------------- shared tiling ----------------
#define NTHREADS 512
#define PITCHB 144                    // (64+8) bf16 * 2B, conflict-free
#define A_BYTES (256 * PITCHB)        // 2 splits x 128 rows
#define B_BYTES (384 * PITCHB)        // 6 regions x 64 rows
#define BUF_BYTES (A_BYTES + B_BYTES) // 92160
#define STEP_SMEM (2 * BUF_BYTES)     // 184320

// warp layout (16 warps): m0w=(warp&3)*32, n0w=(warp>>2)*16
// per-warp tile: 32 rows x 16 cols x 3 mats; acc[3][2][2][4]
#define COMPUTE_CHUNK(bb)                                                        \
    do {                                                                         \
        const uint32_t Abase = sbase + (bb) * BUF_BYTES;                         \
        const uint32_t Bbase = Abase + A_BYTES;                                  \
        _Pragma("unroll")                                                        \
        for (int q = 0; q < 4; q++) {                                            \
            const uint32_t koff = q * 32 + tig * 4;                              \
            uint32_t ahi[2][4], alo[2][4];                                       \
            _Pragma("unroll")                                                    \
            for (int f = 0; f < 2; f++) {                                        \
                uint32_t rh = Abase + (uint32_t)((m0w + f * 16 + group) * PITCHB) + koff; \
                ahi[f][0] = lds32(rh);                                           \
                ahi[f][1] = lds32(rh + 8 * PITCHB);                              \
                ahi[f][2] = lds32(rh + 16);                                      \
                ahi[f][3] = lds32(rh + 8 * PITCHB + 16);                         \
                uint32_t rl = rh + 128 * PITCHB;                                 \
                alo[f][0] = lds32(rl);                                           \
                alo[f][1] = lds32(rl + 8 * PITCHB);                              \
                alo[f][2] = lds32(rl + 16);                                      \
                alo[f][3] = lds32(rl + 8 * PITCHB + 16);                         \
            }                                                                    \
            _Pragma("unroll")                                                    \
            for (int mat = 0; mat < 3; mat++) {                                  \
                uint32_t bh[2][2], bl[2][2];                                     \
                _Pragma("unroll")                                                \
                for (int j = 0; j < 2; j++) {                                    \
                    uint32_t rbh = Bbase +                                       \
                        (uint32_t)(((mat * 2) * 64 + n0w + j * 8 + group) * PITCHB) + koff; \
                    bh[j][0] = lds32(rbh); bh[j][1] = lds32(rbh + 16);           \
                    uint32_t rbl = rbh + 64 * PITCHB;                            \
                    bl[j][0] = lds32(rbl); bl[j][1] = lds32(rbl + 16);           \
                }                                                                \
                _Pragma("unroll")                                                \
                for (int j = 0; j < 2; j++)                                      \
                    { mma_bf16(acc[mat][0][j], ahi[0], bh[j]);                   \
                      mma_bf16(acc[mat][1][j], ahi[1], bh[j]); }                 \
                _Pragma("unroll")                                                \
                for (int j = 0; j < 2; j++)                                      \
                    { mma_bf16(acc[mat][0][j], ahi[0], bl[j]);                   \
                      mma_bf16(acc[mat][1][j], ahi[1], bl[j]); }                 \
                _Pragma("unroll")                                                \
                for (int j = 0; j < 2; j++)                                      \
                    { mma_bf16(acc[mat][0][j], alo[0], bh[j]);                   \
                      mma_bf16(acc[mat][1][j], alo[1], bh[j]); }                 \
            }                                                                    \
        }                                                                        \
    } while (0)

// =========================================================================
// proj kernel via mma.sync: rows m = t*4096+b, K=192 (3 chunks)
// grid (2048, 4), 512 threads
// =========================================================================
__global__ __launch_bounds__(NTHREADS, 1) void proj_mma_kernel(
    const float* __restrict__ x,
    const float* __restrict__ bfa, const float* __restrict__ bfb,
    const float* __restrict__ bga, const float* __restrict__ bgb,
    const float* __restrict__ bta, const float* __restrict__ btb)
{
    extern __shared__ char sm[];
    const uint32_t sbase = smem_to_u32(sm);

    const int tid   = threadIdx.x;
    const int warp  = tid >> 5;
    const int lane  = tid & 31;
    const int group = lane >> 2;
    const int tig   = lane & 3;
    const int m0    = blockIdx.x * 128;
    const int n0    = blockIdx.y * 64;
    const int m0w   = (warp & 3) * 32;
    const int n0w   = (warp >> 2) * 16;
    const int tq    = m0 >> 12;
    const int bq0   = m0 & 4095;

    float acc[3][2][2][4] = {};

    auto stageA = [&](int chunk, int bb) {
        const uint32_t dstb = sbase + bb * BUF_BYTES;
        #pragma unroll
        for (int j = 0; j < 4; j++) {
            int u   = tid + j * NTHREADS;   // 0..2047 float4 units
            int row = u >> 4;
            int f4  = u & 15;
            float4 v = *(const float4*)&x[((((size_t)(bq0 + row) * 3 + chunk) << 6) + tq) * 64 + f4 * 4];
            uint32_t base = dstb + (uint32_t)(row * PITCHB + f4 * 8);
            sts64(base, pack_hi2(v.x, v.y), pack_hi2(v.z, v.w));
            sts64(base + 128 * PITCHB, pack_lo2(v.x, v.y), pack_lo2(v.z, v.w));
        }
    };
    auto stageB = [&](int chunk, int bb) {
        const int kc0 = chunk * 64;
        const uint32_t dstb = sbase + bb * BUF_BYTES + A_BYTES;
        #pragma unroll
        for (int j = 0; j < 6; j++) {
            int u = tid + j * NTHREADS;
            int rg = u >> 9, row = (u >> 3) & 63, kb = u & 7;
            int mat = rg >> 1, sp = rg & 1;
            const __nv_bfloat16* src =
                &g_wbf_in[mat][sp][(size_t)(n0 + row) * INDIM + kc0 + kb * 8];
            uint32_t dst = dstb + (uint32_t)((rg * 64 + row) * PITCHB + kb * 16);
            CP_ASYNC16(dst, src);
        }
    };

    stageB(0, 0); CP_COMMIT();
    stageA(0, 0);
    #pragma unroll 1
    for (int c = 0; c < 3; c++) {
        if (c < 2) {
            stageB(c + 1, (c + 1) & 1); CP_COMMIT();
            stageA(c + 1, (c + 1) & 1);
            CP_WAIT(1);
        } else {
            CP_WAIT(0);
        }
        __syncthreads();
        COMPUTE_CHUNK(c & 1);
        __syncthreads();
    }

    const float* inb[3]  = {bfa, bga, bta};
    const float* hbb[3]  = {bfb, bgb, btb};
    #pragma unroll
    for (int f = 0; f < 2; f++) {
        #pragma unroll
        for (int hh = 0; hh < 2; hh++) {
            const int m = m0w + f * 16 + group + hh * 8;
            const size_t obase = (size_t)(m0 + m) * HID;
            #pragma unroll
            for (int j = 0; j < 2; j++) {
                const int jabs = n0 + n0w + j * 8 + tig * 2;
                #pragma unroll
                for (int mat = 0; mat < 3; mat++) {
                    float2 bi = *(const float2*)&inb[mat][jabs];
                    float2 bh2 = *(const float2*)&hbb[mat][jabs];
                    float2 o;
                    o.x = acc[mat][f][j][hh * 2]     + bi.x + bh2.x;
                    o.y = acc[mat][f][j][hh * 2 + 1] + bi.y + bh2.y;
                    *(float2*)&g_proj[mat][obase + jabs] = o;
                }
            }
        }
    }
}

// =========================================================================
// recurrent step via mma.sync bf16 split-precision, 512 threads
// =========================================================================
__global__ __launch_bounds__(NTHREADS, 1) void step_mma_kernel(int t)
{
    extern __shared__ char sm[];
    const uint32_t sbase = smem_to_u32(sm);

    const float* __restrict__ hin = g_h[t & 1];
    float* __restrict__ hout      = g_h[(t + 1) & 1];
    const __nv_bfloat16* __restrict__ hbf_hi = g_hbf[t & 1][0];
    const __nv_bfloat16* __restrict__ hbf_lo = g_hbf[t & 1][1];

    const int tid   = threadIdx.x;
    const int warp  = tid >> 5;
    const int lane  = tid & 31;
    const int group = lane >> 2;
    const int tig   = lane & 3;
    const int b0    = blockIdx.x * 128;
    const int n0    = blockIdx.y * 64;
    const int m0w   = (warp & 3) * 32;
    const int n0w   = (warp >> 2) * 16;

    float acc[3][2][2][4] = {};

    auto stage = [&](int chunk, int bb) {
        const int kc0 = chunk * 64;
        const uint32_t dstb = sbase + bb * BUF_BYTES;
        #pragma unroll
        for (int j = 0; j < 4; j++) {
            int u = tid + j * NTHREADS;
            int s = u >> 10, row = (u >> 3) & 127, kb = u & 7;
            const __nv_bfloat16* src =
                (s == 0 ? hbf_hi : hbf_lo) + (size_t)(b0 + row) * HID + kc0 + kb * 8;
            uint32_t dst = dstb + (uint32_t)((s * 128 + row) * PITCHB + kb * 16);
            CP_ASYNC16(dst, src);
        }
        #pragma unroll
        for (int j = 0; j < 6; j++) {
            int u = tid + j * NTHREADS;
            int rg = u >> 9, row = (u >> 3) & 63, kb = u & 7;
            int mat = rg >> 1, sp = rg & 1;
            const __nv_bfloat16* src =
                &g_wbf[mat][sp][(size_t)(n0 + row) * HID + kc0 + kb * 8];
            uint32_t dst = dstb + A_BYTES + (uint32_t)((rg * 64 + row) * PITCHB + kb * 16);
            CP_ASYNC16(dst, src);
        }
    };

    stage(0, 0);
    CP_COMMIT();
    #pragma unroll 1
    for (int c = 0; c < 4; c++) {
        if (c < 3) {
            stage(c + 1, (c + 1) & 1);
            CP_COMMIT();
            CP_WAIT(1);
        } else {
            CP_WAIT(0);
        }
        __syncthreads();
        COMPUTE_CHUNK(c & 1);
        __syncthreads();
    }

    // ---- fused LTC epilogue ----
    #pragma unroll
    for (int f = 0; f < 2; f++) {
        #pragma unroll
        for (int hh = 0; hh < 2; hh++) {
            const int m = m0w + f * 16 + group + hh * 8;
            const int b = b0 + m;
            const size_t hrow  = (size_t)b * HID;
            const size_t pbase = ((size_t)t * BATCH + b) * HID;
            #pragma unroll
            for (int j = 0; j < 2; j++) {
                const int jabs = n0 + n0w + j * 8 + tig * 2;
                float2 pf = *(const float2*)&g_proj[0][pbase + jabs];
                float2 pg = *(const float2*)&g_proj[1][pbase + jabs];
                float2 pt = *(const float2*)&g_proj[2][pbase + jabs];
                float2 hv = *(const float2*)&hin[hrow + jabs];
                float o2[2];
                #pragma unroll
                for (int e = 0; e < 2; e++) {
                    float rf = acc[0][f][j][hh * 2 + e];
                    float rg = acc[1][f][j][hh * 2 + e];
                    float rt = acc[2][f][j][hh * 2 + e];
                    float pfe = e ? pf.y : pf.x;
                    float pge = e ? pg.y : pg.x;
                    float pte = e ? pt.y : pt.x;
                    float hve = e ? hv.y : hv.x;
                    float e2 = __expf(2.f * (pfe + rf));
                    float cand = (e2 - 1.f) / (e2 + 1.f);
                    float gate = 1.f / (1.f + __expf(-(pge + rg)));
                    float tau  = 0.5f + 1.5f / (1.f + __expf(-(pte + rt)));
                    float hn = hve + (gate * cand - hve) / tau;
                    float e2h = __expf(2.f * hn);
                    o2[e] = (e2h - 1.f) / (e2h + 1.f);
                }
                *(float2*)&hout[hrow + jabs] = make_float2(o2[0], o2[1]);
                *(uint32_t*)&g_hbf[(t + 1) & 1][0][hrow + jabs] = pack_hi2(o2[0], o2[1]);
                *(uint32_t*)&g_hbf[(t + 1) & 1][1][hrow + jabs] = pack_lo2(o2[0], o2[1]);
            }
        }
    }
}

// ---------------- head ----------------
__global__ void head_kernel(const float* __restrict__ hw,
                            const float* __restrict__ hb,
                            float* __restrict__ out)
{
    int gwarp = (blockIdx.x * blockDim.x + threadIdx.x) >> 5;
    int lane  = threadIdx.x & 31;
    if (gwarp >= BATCH * 10) return;
    int o = gwarp % 10;
    int b = gwarp / 10;
    const float* h = g_h[0];   // T=64 even -> final state in buffer 0
    float s = 0.f;
    #pragma unroll
    for (int k = lane; k < HID; k += 32)
        s += h[b * HID + k] * hw[o * HID + k];
    #pragma unroll
    for (int off = 16; off; off >>= 1)
        s += __shfl_down_sync(0xffffffffu, s, off);
    if (lane == 0) out[b * 10 + o] = s + hb[o];
}

extern "C" void kernel_launch(void* const* d_in, const int* in_sizes, int n_in,
                              void* d_out, int out_size)
{
    const float* x      = (const float*)d_in[0];
    const float* ffw    = (const float*)d_in[1];
    const float* ffb    = (const float*)d_in[2];
    const float* ffrw   = (const float*)d_in[3];
    const float* ffbias = (const float*)d_in[4];
    const float* gw     = (const float*)d_in[5];
    const float* gb     = (const float*)d_in[6];
    const float* grw    = (const float*)d_in[7];
    const float* gbias  = (const float*)d_in[8];
    const float* tw     = (const float*)d_in[9];
    const float* tb     = (const float*)d_in[10];
    const float* trw    = (const float*)d_in[11];
    const float* tbias  = (const float*)d_in[12];
    const float* hw     = (const float*)d_in[13];
    const float* hb     = (const float*)d_in[14];
    float* out = (float*)d_out;

    cudaFuncSetAttribute(step_mma_kernel,
                         cudaFuncAttributeMaxDynamicSharedMemorySize, STEP_SMEM);
    cudaFuncSetAttribute(proj_mma_kernel,
                         cudaFuncAttributeMaxDynamicSharedMemorySize, STEP_SMEM);

    // h0 = 0 (fp32 + bf16 hi/lo)
    zero_h_kernel<<<(BATCH * HID + 255) / 256, 256>>>();

    // W (recurrent + input) -> bf16 hi/lo scratch
    wprep_kernel<<<(HID * HID + 255) / 256, 256>>>(ffrw, grw, trw, ffw, gw, tw);

    // all input projections on the tensor pipe
    dim3 pgrid((T * BATCH) / 128, HID / 64);
    proj_mma_kernel<<<pgrid, NTHREADS, STEP_SMEM>>>(x, ffb, ffbias, gb, gbias, tb, tbias);

    // 64 sequential LTC steps on the tensor pipe
    dim3 sgrid(BATCH / 128, HID / 64);
    for (int t = 0; t < T; t++)
        step_mma_kernel<<<sgrid, NTHREADS, STEP_SMEM>>>(t);

    // classifier head
    head_kernel<<<(BATCH * 10 * 32 + 255) / 256, 256>>>(hw, hb, out);
}